// round 1
// baseline (speedup 1.0000x reference)
#include <cuda_runtime.h>
#include <cstddef>

#define SEQ  3584
#define DIMN 2048
#define NHEAD 16
#define HD   128
#define MQ   3072

// Scratch (alloc-free rule: __device__ globals)
__device__ float g_q[SEQ * DIMN];
__device__ float g_k[SEQ * DIMN];
__device__ float g_v[SEQ * DIMN];
__device__ float g_o[SEQ * DIMN];

// ---------------------------------------------------------------------------
// GEMM: C[M,N] = A[M,K] @ W[N,K]^T + bias[N]
// Tiles: BM=128, BN=64, BK=16. 256 threads, 8x4 microtile per thread.
// ---------------------------------------------------------------------------
__global__ void __launch_bounds__(256) gemm_bias(const float* __restrict__ A,
                                                 const float* __restrict__ W,
                                                 const float* __restrict__ bias,
                                                 float* __restrict__ C,
                                                 int M, int N, int K)
{
    __shared__ float As[16][128];
    __shared__ float Bs[16][64];
    const int tid = threadIdx.x;
    const int tx = tid & 15;
    const int ty = tid >> 4;
    const int m0 = blockIdx.y * 128;
    const int n0 = blockIdx.x * 64;

    float acc[8][4];
#pragma unroll
    for (int i = 0; i < 8; i++)
#pragma unroll
        for (int j = 0; j < 4; j++) acc[i][j] = 0.f;

    const int ar = tid >> 2;        // 0..63
    const int ac = (tid & 3) * 4;   // 0,4,8,12

    for (int k0 = 0; k0 < K; k0 += 16) {
#pragma unroll
        for (int rep = 0; rep < 2; rep++) {
            int r = ar + rep * 64;
            float4 av = *(const float4*)&A[(size_t)(m0 + r) * K + k0 + ac];
            As[ac + 0][r] = av.x; As[ac + 1][r] = av.y;
            As[ac + 2][r] = av.z; As[ac + 3][r] = av.w;
        }
        {
            float4 bv = *(const float4*)&W[(size_t)(n0 + ar) * K + k0 + ac];
            Bs[ac + 0][ar] = bv.x; Bs[ac + 1][ar] = bv.y;
            Bs[ac + 2][ar] = bv.z; Bs[ac + 3][ar] = bv.w;
        }
        __syncthreads();
#pragma unroll
        for (int kk = 0; kk < 16; kk++) {
            float a[8], b[4];
            *(float4*)&a[0] = *(const float4*)&As[kk][ty * 8];
            *(float4*)&a[4] = *(const float4*)&As[kk][ty * 8 + 4];
            *(float4*)&b[0] = *(const float4*)&Bs[kk][tx * 4];
#pragma unroll
            for (int i = 0; i < 8; i++)
#pragma unroll
                for (int j = 0; j < 4; j++)
                    acc[i][j] = fmaf(a[i], b[j], acc[i][j]);
        }
        __syncthreads();
    }

    float4 bv = *(const float4*)&bias[n0 + tx * 4];
#pragma unroll
    for (int i = 0; i < 8; i++) {
        float4 ov;
        ov.x = acc[i][0] + bv.x;
        ov.y = acc[i][1] + bv.y;
        ov.z = acc[i][2] + bv.z;
        ov.w = acc[i][3] + bv.w;
        *(float4*)&C[(size_t)(m0 + ty * 8 + i) * N + n0 + tx * 4] = ov;
    }
}

// ---------------------------------------------------------------------------
// RMSNorm over DIM=2048 (+ scale g) then RoPE (in-place on q/k).
// grid (SEQ, 2): y=0 -> q with gq, y=1 -> k with gk. 256 threads / row.
// Pair p (0..1023): head-pair hp = p & 63; hp<22 uses frame pos, <43 uses h, else w.
// ---------------------------------------------------------------------------
__global__ void __launch_bounds__(256) rms_rope(float* __restrict__ q,
                                                float* __restrict__ k,
                                                const float* __restrict__ gq,
                                                const float* __restrict__ gk,
                                                const float* __restrict__ freqs)
{
    const int row = blockIdx.x;
    const int which = blockIdx.y;
    float* rowp = (which ? k : q) + (size_t)row * DIMN;
    const float* g = which ? gk : gq;
    const int tid = threadIdx.x;

    float ss = 0.f;
    for (int i = tid; i < DIMN; i += 256) { float v = rowp[i]; ss += v * v; }
#pragma unroll
    for (int o = 16; o > 0; o >>= 1) ss += __shfl_xor_sync(0xffffffffu, ss, o);

    __shared__ float wsum[8];
    __shared__ float sinvs;
    if ((tid & 31) == 0) wsum[tid >> 5] = ss;
    __syncthreads();
    if (tid == 0) {
        float t = 0.f;
#pragma unroll
        for (int i = 0; i < 8; i++) t += wsum[i];
        sinvs = rsqrtf(t * (1.0f / (float)DIMN) + 1e-6f);
    }
    __syncthreads();
    const float inv = sinvs;

    int f, h, w;
    if (row < MQ) { f = row >> 8; int rem = row & 255; h = rem >> 4; w = rem & 15; }
    else { int rr = row - MQ; f = 12 + (rr >> 8); int rem = rr & 255; h = rem >> 4; w = rem & 15; }

    for (int p = tid; p < DIMN / 2; p += 256) {
        int hp = p & 63;
        int pos = (hp < 22) ? f : ((hp < 43) ? h : w);
        float c = freqs[(pos * 64 + hp) * 2 + 0];
        float s = freqs[(pos * 64 + hp) * 2 + 1];
        float e = rowp[2 * p]     * inv * g[2 * p];
        float o = rowp[2 * p + 1] * inv * g[2 * p + 1];
        rowp[2 * p]     = e * c - o * s;
        rowp[2 * p + 1] = e * s + o * c;
    }
}

// ---------------------------------------------------------------------------
// Flash attention, fp32. Q tile 64 x 128, K/V tile 64 x 128, 256 threads.
// Mask is pure range restriction:
//   q-tile < 48 (rows < 3072): attend all 56 k-tiles.
//   q-tile >= 48: cond block j = (qt-48)/4, attend k-tiles [48+4j, 48+4j+4).
// Smem (dynamic, 84480 B): Qs[128][65] (transposed), KV buffer reused for
// K-transposed[128][65] then V[64][132], Ps[64][65], stats.
// ---------------------------------------------------------------------------
#define QPAD 65
#define VPAD 132
#define SM_KV_OFF (128 * QPAD)              // 8320
#define SM_PS_OFF (SM_KV_OFF + 8448)        // KV region 8448 floats
#define SM_ST_OFF (SM_PS_OFF + 64 * QPAD)
#define FLASH_SMEM_BYTES ((SM_ST_OFF + 192) * 4)

__global__ void __launch_bounds__(256) flash_attn(const float* __restrict__ q,
                                                  const float* __restrict__ k,
                                                  const float* __restrict__ v,
                                                  float* __restrict__ o)
{
    extern __shared__ float sm[];
    float* Qs   = sm;
    float* KV   = sm + SM_KV_OFF;
    float* Ps   = sm + SM_PS_OFF;
    float* mrow = sm + SM_ST_OFF;
    float* lrow = mrow + 64;
    float* arow = lrow + 64;

    const int tid = threadIdx.x;
    const int tx = tid & 15, ty = tid >> 4;
    const int qt = blockIdx.x;
    const int head = blockIdx.y;
    const int q0 = qt * 64;
    const float scale = 0.08838834764831845f;  // 1/sqrt(128)

    // Load Q tile transposed + pre-scale
    for (int idx = tid; idx < 64 * 128; idx += 256) {
        int i = idx >> 7, d = idx & 127;
        Qs[d * QPAD + i] = q[(size_t)(q0 + i) * DIMN + head * HD + d] * scale;
    }
    if (tid < 64) { mrow[tid] = -1e30f; lrow[tid] = 0.f; }

    float acc[4][8];
#pragma unroll
    for (int i = 0; i < 4; i++)
#pragma unroll
        for (int j = 0; j < 8; j++) acc[i][j] = 0.f;

    int ktb, kte;
    if (qt < 48) { ktb = 0; kte = 56; }
    else { int j = (qt - 48) >> 2; ktb = 48 + j * 4; kte = ktb + 4; }

    __syncthreads();

    for (int kt = ktb; kt < kte; kt++) {
        const int k0 = kt * 64;

        // K tile, transposed [d][j]
        for (int idx = tid; idx < 64 * 128; idx += 256) {
            int j = idx >> 7, d = idx & 127;
            KV[d * QPAD + j] = k[(size_t)(k0 + j) * DIMN + head * HD + d];
        }
        __syncthreads();

        // S = Q K^T  (64x64, 4x4 per thread)
        float s[4][4];
#pragma unroll
        for (int i = 0; i < 4; i++)
#pragma unroll
            for (int j = 0; j < 4; j++) s[i][j] = 0.f;

#pragma unroll 4
        for (int d = 0; d < 128; d++) {
            float qa[4], kb[4];
#pragma unroll
            for (int i = 0; i < 4; i++) qa[i] = Qs[d * QPAD + ty * 4 + i];
#pragma unroll
            for (int j = 0; j < 4; j++) kb[j] = KV[d * QPAD + tx * 4 + j];
#pragma unroll
            for (int i = 0; i < 4; i++)
#pragma unroll
                for (int j = 0; j < 4; j++)
                    s[i][j] = fmaf(qa[i], kb[j], s[i][j]);
        }
#pragma unroll
        for (int i = 0; i < 4; i++)
#pragma unroll
            for (int j = 0; j < 4; j++)
                Ps[(ty * 4 + i) * QPAD + tx * 4 + j] = s[i][j];
        __syncthreads();

        // Overwrite KV with V tile [j][d] (S done; softmax only touches Ps)
        for (int idx = tid; idx < 64 * 128; idx += 256) {
            int j = idx >> 7, d = idx & 127;
            KV[j * VPAD + d] = v[(size_t)(k0 + j) * DIMN + head * HD + d];
        }

        // Online softmax: one thread per row
        if (tid < 64) {
            int r = tid;
            float mold = mrow[r];
            float mx = mold;
            for (int j = 0; j < 64; j++) mx = fmaxf(mx, Ps[r * QPAD + j]);
            float a = __expf(mold - mx);
            float sum = 0.f;
            for (int j = 0; j < 64; j++) {
                float pz = __expf(Ps[r * QPAD + j] - mx);
                Ps[r * QPAD + j] = pz;
                sum += pz;
            }
            lrow[r] = lrow[r] * a + sum;
            mrow[r] = mx;
            arow[r] = a;
        }
        __syncthreads();

        // Rescale accumulators
#pragma unroll
        for (int i = 0; i < 4; i++) {
            float a = arow[ty * 4 + i];
#pragma unroll
            for (int j = 0; j < 8; j++) acc[i][j] *= a;
        }

        // O += P V   (each thread: rows ty*4..+3, dims tx*8..+7)
        for (int j = 0; j < 64; j++) {
            float pr[4];
#pragma unroll
            for (int i = 0; i < 4; i++) pr[i] = Ps[(ty * 4 + i) * QPAD + j];
            float4 v0 = *(const float4*)&KV[j * VPAD + tx * 8];
            float4 v1 = *(const float4*)&KV[j * VPAD + tx * 8 + 4];
#pragma unroll
            for (int i = 0; i < 4; i++) {
                acc[i][0] = fmaf(pr[i], v0.x, acc[i][0]);
                acc[i][1] = fmaf(pr[i], v0.y, acc[i][1]);
                acc[i][2] = fmaf(pr[i], v0.z, acc[i][2]);
                acc[i][3] = fmaf(pr[i], v0.w, acc[i][3]);
                acc[i][4] = fmaf(pr[i], v1.x, acc[i][4]);
                acc[i][5] = fmaf(pr[i], v1.y, acc[i][5]);
                acc[i][6] = fmaf(pr[i], v1.z, acc[i][6]);
                acc[i][7] = fmaf(pr[i], v1.w, acc[i][7]);
            }
        }
        __syncthreads();
    }

    // Epilogue: normalize and store
#pragma unroll
    for (int i = 0; i < 4; i++) {
        int r = ty * 4 + i;
        float invl = 1.0f / lrow[r];
        float4 o0, o1;
        o0.x = acc[i][0] * invl; o0.y = acc[i][1] * invl;
        o0.z = acc[i][2] * invl; o0.w = acc[i][3] * invl;
        o1.x = acc[i][4] * invl; o1.y = acc[i][5] * invl;
        o1.z = acc[i][6] * invl; o1.w = acc[i][7] * invl;
        *(float4*)&o[(size_t)(q0 + r) * DIMN + head * HD + tx * 8]     = o0;
        *(float4*)&o[(size_t)(q0 + r) * DIMN + head * HD + tx * 8 + 4] = o1;
    }
}

// ---------------------------------------------------------------------------
// Launch
// Inputs: 0 x, 1 Wq, 2 bq, 3 Wk, 4 bk, 5 Wv, 6 bv, 7 Wo, 8 bo,
//         9 gq, 10 gk, 11 freqs, 12 T, 13 H, 14 W, 15 cond_len, 16 cond_non_human
// ---------------------------------------------------------------------------
extern "C" void kernel_launch(void* const* d_in, const int* in_sizes, int n_in,
                              void* d_out, int out_size)
{
    (void)in_sizes; (void)n_in; (void)out_size;
    const float* x     = (const float*)d_in[0];
    const float* Wq    = (const float*)d_in[1];
    const float* bq    = (const float*)d_in[2];
    const float* Wk    = (const float*)d_in[3];
    const float* bk    = (const float*)d_in[4];
    const float* Wv    = (const float*)d_in[5];
    const float* bv    = (const float*)d_in[6];
    const float* Wo    = (const float*)d_in[7];
    const float* bo    = (const float*)d_in[8];
    const float* gq    = (const float*)d_in[9];
    const float* gk    = (const float*)d_in[10];
    const float* freqs = (const float*)d_in[11];
    float* out = (float*)d_out;

    float *pq, *pk, *pv, *po;
    cudaGetSymbolAddress((void**)&pq, g_q);
    cudaGetSymbolAddress((void**)&pk, g_k);
    cudaGetSymbolAddress((void**)&pv, g_v);
    cudaGetSymbolAddress((void**)&po, g_o);

    cudaFuncSetAttribute(flash_attn, cudaFuncAttributeMaxDynamicSharedMemorySize,
                         FLASH_SMEM_BYTES);

    dim3 ggrid(DIMN / 64, SEQ / 128);
    gemm_bias<<<ggrid, 256>>>(x, Wq, bq, pq, SEQ, DIMN, DIMN);
    gemm_bias<<<ggrid, 256>>>(x, Wk, bk, pk, SEQ, DIMN, DIMN);
    gemm_bias<<<ggrid, 256>>>(x, Wv, bv, pv, SEQ, DIMN, DIMN);

    rms_rope<<<dim3(SEQ, 2), 256>>>(pq, pk, gq, gk, freqs);

    flash_attn<<<dim3(SEQ / 64, NHEAD), 256, FLASH_SMEM_BYTES>>>(pq, pk, pv, po);

    gemm_bias<<<ggrid, 256>>>(po, Wo, bo, out, SEQ, DIMN, DIMN);
}